// round 12
// baseline (speedup 1.0000x reference)
#include <cuda_runtime.h>
#include <cuda_fp16.h>
#include <cstdint>

// AntisymmetricLayer via fp16 mma.sync.m16n8k16 (fp32 accum).
//   z = x1-x2, s = x1+x2 (fp16)
//   Phase L: lin = z @ W^T -> out (W fragment-packed per warp)
//   Main: per 4-k group, zP = z @ P^T, sQ = s @ Q^T; epilogue RMW out += sum_r zP*sQ
// r12 = r11 with the M-row indexing fixed: row base is wm*(MI*16)+mi*16 (4 M-warps x
// MI m16-tiles exactly cover the tile; r11's wm*(MI*32) overflowed the tile -> IMA).
//   THREADS=256, MTILE=128, warps 4M x 2N, warp tile 32x32 (MI=2), occ 2 (16 warps/SM).
//   B fragment-packed, LDG from L1/L2; no staging, no main-loop barriers.
//   Mixed grid: 888 full tiles (3 exact waves) + 272 half tiles.

#define D128 128
#define KTOT 64
#define NGRP 16
#define THREADS 256

#define ZSH 0
#define SSH 32768
#define SMEM_BYTES 65536

// fragment-packed B: [g][ks][wn][j] blocks of 512B (32 lanes x 16B = P.b0,b1,Q.b0,b1)
__device__ __align__(16) __half g_B[16 * 8 * 2 * 4 * 256];
// fragment-packed W: [ks][wn][t] blocks of 256B (32 lanes x 8B)
__device__ __align__(16) __half g_Wt[8 * 2 * 4 * 128];

__device__ __forceinline__ uint32_t smem_u32(const void* p) {
    uint32_t a;
    asm("{ .reg .u64 t; cvta.to.shared.u64 t, %1; cvt.u32.u64 %0, t; }" : "=r"(a) : "l"(p));
    return a;
}

#define LDSM_X4(r0, r1, r2, r3, a) \
    asm volatile("ldmatrix.sync.aligned.m8n8.x4.shared.b16 {%0,%1,%2,%3}, [%4];" \
        : "=r"(r0), "=r"(r1), "=r"(r2), "=r"(r3) : "r"(a))

__device__ __forceinline__ void mma_f16(float* d, const uint32_t* a, const uint32_t* b) {
    asm volatile("mma.sync.aligned.m16n8k16.row.col.f32.f16.f16.f32 "
                 "{%0,%1,%2,%3}, {%4,%5,%6,%7}, {%8,%9}, {%0,%1,%2,%3};"
                 : "+f"(d[0]), "+f"(d[1]), "+f"(d[2]), "+f"(d[3])
                 : "r"(a[0]), "r"(a[1]), "r"(a[2]), "r"(a[3]),
                   "r"(b[0]), "r"(b[1]));
}

// ---- pack P,Q into fragment order ----
__global__ void pack_b(const float* __restrict__ P, const float* __restrict__ Q) {
    int t = blockIdx.x * 256 + threadIdx.x;   // 0..32767
    int l = t & 31, j = (t >> 5) & 3, wn = (t >> 7) & 1, ks = (t >> 8) & 7, g = t >> 11;
    int c = wn * 32 + j * 8 + (l >> 2);
    int k = g * 4 + (c >> 4), r = c & 15;
    int d0 = ks * 16 + 2 * (l & 3);
    __half h[8];
    h[0] = __float2half_rn(P[(k * 128 + d0) * 16 + r]);
    h[1] = __float2half_rn(P[(k * 128 + d0 + 1) * 16 + r]);
    h[2] = __float2half_rn(P[(k * 128 + d0 + 8) * 16 + r]);
    h[3] = __float2half_rn(P[(k * 128 + d0 + 9) * 16 + r]);
    h[4] = __float2half_rn(Q[(k * 128 + d0) * 16 + r]);
    h[5] = __float2half_rn(Q[(k * 128 + d0 + 1) * 16 + r]);
    h[6] = __float2half_rn(Q[(k * 128 + d0 + 8) * 16 + r]);
    h[7] = __float2half_rn(Q[(k * 128 + d0 + 9) * 16 + r]);
    *reinterpret_cast<uint4*>(&g_B[t * 8]) = *reinterpret_cast<uint4*>(h);
}

// ---- pack W ----
__global__ void pack_w(const float* __restrict__ W) {
    int t = blockIdx.x * 256 + threadIdx.x;   // 0..2047
    int l = t & 31, tile = (t >> 5) & 3, wn = (t >> 7) & 1, ks = t >> 8;
    int n = l >> 2;
    int k = 16 * tile + 4 * (n >> 1) + 2 * wn + (n & 1);
    int d0 = ks * 16 + 2 * (l & 3);
    __half h[4];
    h[0] = __float2half_rn(W[k * 128 + d0]);
    h[1] = __float2half_rn(W[k * 128 + d0 + 1]);
    h[2] = __float2half_rn(W[k * 128 + d0 + 8]);
    h[3] = __float2half_rn(W[k * 128 + d0 + 9]);
    *reinterpret_cast<uint2*>(&g_Wt[t * 4]) = *reinterpret_cast<uint2*>(h);
}

// ---------------- tile body, MI = m16-tiles per M-warp (2 = 128-tok tile, 1 = 64) ----
template <int MI>
__device__ __forceinline__ void tile_body(
    const float* __restrict__ x1, const float* __restrict__ x2,
    float* __restrict__ out, char* shm, uint32_t smb, size_t mbase)
{
    const int tid = threadIdx.x;
    const int lane = tid & 31;
    const int wid = tid >> 5;
    const int wm = wid & 3;        // M-warp 0..3 (MI*16 rows each)
    const int wn = wid >> 2;       // N-warp 0..1
    const int g4 = lane >> 2;
    const int c4 = lane & 3;

    // ---- stage z,s as fp16 (swizzled 256B rows) ----
    {
        const float4* x1v = reinterpret_cast<const float4*>(x1) + mbase * 32;
        const float4* x2v = reinterpret_cast<const float4*>(x2) + mbase * 32;
        #pragma unroll
        for (int it = 0; it < MI * 4; it++) {
            int idx = it * THREADS + tid;     // MI*1024 chunks (= tokens*16)
            int m = idx >> 4, c = idx & 15;
            float4 a0 = x1v[m * 32 + c * 2];
            float4 a1 = x1v[m * 32 + c * 2 + 1];
            float4 b0 = x2v[m * 32 + c * 2];
            float4 b1 = x2v[m * 32 + c * 2 + 1];
            half2 zz[4], ss[4];
            zz[0] = __floats2half2_rn(a0.x - b0.x, a0.y - b0.y);
            zz[1] = __floats2half2_rn(a0.z - b0.z, a0.w - b0.w);
            zz[2] = __floats2half2_rn(a1.x - b1.x, a1.y - b1.y);
            zz[3] = __floats2half2_rn(a1.z - b1.z, a1.w - b1.w);
            ss[0] = __floats2half2_rn(a0.x + b0.x, a0.y + b0.y);
            ss[1] = __floats2half2_rn(a0.z + b0.z, a0.w + b0.w);
            ss[2] = __floats2half2_rn(a1.x + b1.x, a1.y + b1.y);
            ss[3] = __floats2half2_rn(a1.z + b1.z, a1.w + b1.w);
            uint32_t so = (uint32_t)(m * 256 + ((c ^ (m & 7)) << 4));
            *reinterpret_cast<uint4*>(shm + ZSH + so) = *reinterpret_cast<uint4*>(zz);
            *reinterpret_cast<uint4*>(shm + SSH + so) = *reinterpret_cast<uint4*>(ss);
        }
    }
    __syncthreads();

    // ---- per-lane A ldmatrix row bases (row base = wm*(MI*16) + mi*16) ----
    const int xr = lane & 7;
    uint32_t rowA[MI];
    #pragma unroll
    for (int mi = 0; mi < MI; mi++)
        rowA[mi] = (uint32_t)((wm * (MI * 16) + mi * 16 + ((lane >> 3) & 1) * 8 + xr) * 256);
    const int krelA = lane >> 4;

    const uint4* bv = reinterpret_cast<const uint4*>(g_B);
    const uint2* wv = reinterpret_cast<const uint2*>(g_Wt);

    // ---- Phase L: lin = z @ W^T ----
    {
        float lw[MI][4][4] = {};
        #pragma unroll
        for (int ks = 0; ks < 8; ks++) {
            uint32_t offA = (uint32_t)(((2 * ks + krelA) ^ xr) << 4);
            uint32_t az[MI][4];
            #pragma unroll
            for (int mi = 0; mi < MI; mi++)
                LDSM_X4(az[mi][0], az[mi][1], az[mi][2], az[mi][3],
                        smb + ZSH + rowA[mi] + offA);
            #pragma unroll
            for (int t = 0; t < 4; t++) {
                uint2 w = wv[((ks * 2 + wn) * 4 + t) * 32 + lane];
                uint32_t bw[2] = {w.x, w.y};
                #pragma unroll
                for (int mi = 0; mi < MI; mi++)
                    mma_f16(lw[mi][t], az[mi], bw);
            }
        }
        #pragma unroll
        for (int mi = 0; mi < MI; mi++) {
            size_t m0 = mbase + wm * (MI * 16) + mi * 16 + g4;
            #pragma unroll
            for (int t = 0; t < 4; t++) {
                int k0 = 16 * t + 4 * c4 + 2 * wn;
                *reinterpret_cast<float2*>(&out[m0 * KTOT + k0]) =
                    make_float2(lw[mi][t][0], lw[mi][t][1]);
                *reinterpret_cast<float2*>(&out[(m0 + 8) * KTOT + k0]) =
                    make_float2(lw[mi][t][2], lw[mi][t][3]);
            }
        }
    }

    // ---- main loop: per k-step 2*MI LDSM + 4 LDG.128 (L1-hot) + 8*MI HMMA ----
    for (int g = 0; g < NGRP; g++) {
        // prefetch this group's lin for the RMW (hides under the MMA chain)
        const int kA = g * 4 + 2 * wn;
        const bool writer = (c4 == (g & 3));
        float2 l0[MI], l1[MI];
        if (writer) {
            #pragma unroll
            for (int mi = 0; mi < MI; mi++) {
                size_t m0 = mbase + wm * (MI * 16) + mi * 16 + g4;
                l0[mi] = *reinterpret_cast<const float2*>(&out[m0 * KTOT + kA]);
                l1[mi] = *reinterpret_cast<const float2*>(&out[(m0 + 8) * KTOT + kA]);
            }
        }

        float zp[MI][4][4] = {};
        float sq[MI][4][4] = {};

        #pragma unroll
        for (int ks = 0; ks < 8; ks++) {
            uint4 v[4];
            const int bb = ((g * 8 + ks) * 2 + wn) * 4;
            #pragma unroll
            for (int j = 0; j < 4; j++) v[j] = bv[(bb + j) * 32 + lane];

            uint32_t offA = (uint32_t)(((2 * ks + krelA) ^ xr) << 4);
            uint32_t az[MI][4], as_[MI][4];
            #pragma unroll
            for (int mi = 0; mi < MI; mi++) {
                LDSM_X4(az[mi][0], az[mi][1], az[mi][2], az[mi][3],
                        smb + ZSH + rowA[mi] + offA);
                LDSM_X4(as_[mi][0], as_[mi][1], as_[mi][2], as_[mi][3],
                        smb + SSH + rowA[mi] + offA);
            }
            #pragma unroll
            for (int j = 0; j < 4; j++) {
                uint32_t bp[2] = {v[j].x, v[j].y};
                uint32_t bq[2] = {v[j].z, v[j].w};
                #pragma unroll
                for (int mi = 0; mi < MI; mi++) {
                    mma_f16(zp[mi][j], az[mi], bp);
                    mma_f16(sq[mi][j], as_[mi], bq);
                }
            }
        }

        // ---- epilogue: reduce r, add prefetched lin, store ----
        #pragma unroll
        for (int mi = 0; mi < MI; mi++) {
            float pa0 = zp[mi][0][0]*sq[mi][0][0] + zp[mi][0][1]*sq[mi][0][1]
                      + zp[mi][1][0]*sq[mi][1][0] + zp[mi][1][1]*sq[mi][1][1];
            float pa1 = zp[mi][0][2]*sq[mi][0][2] + zp[mi][0][3]*sq[mi][0][3]
                      + zp[mi][1][2]*sq[mi][1][2] + zp[mi][1][3]*sq[mi][1][3];
            float pb0 = zp[mi][2][0]*sq[mi][2][0] + zp[mi][2][1]*sq[mi][2][1]
                      + zp[mi][3][0]*sq[mi][3][0] + zp[mi][3][1]*sq[mi][3][1];
            float pb1 = zp[mi][2][2]*sq[mi][2][2] + zp[mi][2][3]*sq[mi][2][3]
                      + zp[mi][3][2]*sq[mi][3][2] + zp[mi][3][3]*sq[mi][3][3];
            pa0 += __shfl_xor_sync(~0u, pa0, 1); pa0 += __shfl_xor_sync(~0u, pa0, 2);
            pa1 += __shfl_xor_sync(~0u, pa1, 1); pa1 += __shfl_xor_sync(~0u, pa1, 2);
            pb0 += __shfl_xor_sync(~0u, pb0, 1); pb0 += __shfl_xor_sync(~0u, pb0, 2);
            pb1 += __shfl_xor_sync(~0u, pb1, 1); pb1 += __shfl_xor_sync(~0u, pb1, 2);
            if (writer) {
                size_t m0 = mbase + wm * (MI * 16) + mi * 16 + g4;
                *reinterpret_cast<float2*>(&out[m0 * KTOT + kA]) =
                    make_float2(l0[mi].x + pa0, l0[mi].y + pb0);
                *reinterpret_cast<float2*>(&out[(m0 + 8) * KTOT + kA]) =
                    make_float2(l1[mi].x + pa1, l1[mi].y + pb1);
            }
        }
    }
}

// ---------------- main kernel ----------------
__global__ __launch_bounds__(THREADS, 2)
void antisym_h(const float* __restrict__ x1, const float* __restrict__ x2,
               float* __restrict__ out, int fullCTAs)
{
    extern __shared__ char shm[];
    const uint32_t smb = smem_u32(shm);
    const int bid = blockIdx.x;

    if (bid < fullCTAs) {
        tile_body<2>(x1, x2, out, shm, smb, (size_t)bid * 128);
    } else {
        tile_body<1>(x1, x2, out, shm, smb,
                     (size_t)fullCTAs * 128 + (size_t)(bid - fullCTAs) * 64);
    }
}

extern "C" void kernel_launch(void* const* d_in, const int* in_sizes, int n_in,
                              void* d_out, int out_size)
{
    const float* x1 = (const float*)d_in[0];
    const float* x2 = (const float*)d_in[1];
    const float* W  = (const float*)d_in[2];
    const float* P  = (const float*)d_in[3];
    const float* Q  = (const float*)d_in[4];
    float* out = (float*)d_out;

    pack_b<<<128, 256>>>(P, Q);
    pack_w<<<8, 256>>>(W);

    const int tokens = in_sizes[0] / D128;        // 131072
    const int tiles128 = tokens / 128;            // 1024
    const int CONC = 296;                         // 148 SMs x occ 2
    int full = (tiles128 / CONC) * CONC;          // 888
    if (full == 0) full = tiles128;
    const int smallCTAs = (tokens - full * 128) / 64;   // 272
    const int grid = full + smallCTAs;            // 1160

    cudaFuncSetAttribute(antisym_h,
                         cudaFuncAttributeMaxDynamicSharedMemorySize, SMEM_BYTES);
    antisym_h<<<grid, THREADS, SMEM_BYTES>>>(x1, x2, out, full);
}

// round 13
// speedup vs baseline: 1.0989x; 1.0989x over previous
#include <cuda_runtime.h>
#include <cuda_fp16.h>
#include <cstdint>

// AntisymmetricLayer via fp16 mma.sync.m16n8k16 (fp32 accum).
//   z = x1-x2, s = x1+x2 (fp16)
//   Phase L: lin = z @ W^T -> out (W fragment-packed per warp)
//   Main: per 4-k group, zP = z @ P^T, sQ = s @ Q^T; epilogue RMW out += sum_r zP*sQ
// r13 = r9 (best, 195us: MTILE=128, 4 warps 2Mx2N, warp tile 64x32, occ 2,
// fragment-packed B from L2, no staging, no main-loop barriers, mixed-grid tail) plus:
//   - lin RMW prefetch hoisted to group start (hides ~250cyc L2 hit under the MMA chain)
//   - branchless one-step-ahead B prefetch via zeroed pad group

#define D128 128
#define KTOT 64
#define NGRP 16
#define THREADS 128

#define ZSH 0
#define SSH 32768
#define SMEM_BYTES 65536

// fragment-packed B (+1 zero pad group for branchless prefetch):
// [g][ks][wn][j] blocks of 512B (32 lanes x 16B = P.b0,b1,Q.b0,b1)
__device__ __align__(16) __half g_B[(16 + 1) * 8 * 2 * 4 * 256];
// fragment-packed W: [ks][wn][t] blocks of 256B (32 lanes x 8B)
__device__ __align__(16) __half g_Wt[8 * 2 * 4 * 128];

__device__ __forceinline__ uint32_t smem_u32(const void* p) {
    uint32_t a;
    asm("{ .reg .u64 t; cvta.to.shared.u64 t, %1; cvt.u32.u64 %0, t; }" : "=r"(a) : "l"(p));
    return a;
}

#define LDSM_X4(r0, r1, r2, r3, a) \
    asm volatile("ldmatrix.sync.aligned.m8n8.x4.shared.b16 {%0,%1,%2,%3}, [%4];" \
        : "=r"(r0), "=r"(r1), "=r"(r2), "=r"(r3) : "r"(a))

__device__ __forceinline__ void mma_f16(float* d, const uint32_t* a, const uint32_t* b) {
    asm volatile("mma.sync.aligned.m16n8k16.row.col.f32.f16.f16.f32 "
                 "{%0,%1,%2,%3}, {%4,%5,%6,%7}, {%8,%9}, {%0,%1,%2,%3};"
                 : "+f"(d[0]), "+f"(d[1]), "+f"(d[2]), "+f"(d[3])
                 : "r"(a[0]), "r"(a[1]), "r"(a[2]), "r"(a[3]),
                   "r"(b[0]), "r"(b[1]));
}

// ---- pack P,Q into fragment order ----
__global__ void pack_b(const float* __restrict__ P, const float* __restrict__ Q) {
    int t = blockIdx.x * 256 + threadIdx.x;   // 0..32767
    int l = t & 31, j = (t >> 5) & 3, wn = (t >> 7) & 1, ks = (t >> 8) & 7, g = t >> 11;
    int c = wn * 32 + j * 8 + (l >> 2);
    int k = g * 4 + (c >> 4), r = c & 15;
    int d0 = ks * 16 + 2 * (l & 3);
    __half h[8];
    h[0] = __float2half_rn(P[(k * 128 + d0) * 16 + r]);
    h[1] = __float2half_rn(P[(k * 128 + d0 + 1) * 16 + r]);
    h[2] = __float2half_rn(P[(k * 128 + d0 + 8) * 16 + r]);
    h[3] = __float2half_rn(P[(k * 128 + d0 + 9) * 16 + r]);
    h[4] = __float2half_rn(Q[(k * 128 + d0) * 16 + r]);
    h[5] = __float2half_rn(Q[(k * 128 + d0 + 1) * 16 + r]);
    h[6] = __float2half_rn(Q[(k * 128 + d0 + 8) * 16 + r]);
    h[7] = __float2half_rn(Q[(k * 128 + d0 + 9) * 16 + r]);
    *reinterpret_cast<uint4*>(&g_B[t * 8]) = *reinterpret_cast<uint4*>(h);
}

// ---- zero the pad group ----
__global__ void pad_b() {
    int t = blockIdx.x * 256 + threadIdx.x;   // 0..2047
    *reinterpret_cast<uint4*>(&g_B[(16 * 8 * 2 * 4 * 256) + t * 8]) =
        make_uint4(0u, 0u, 0u, 0u);
}

// ---- pack W ----
__global__ void pack_w(const float* __restrict__ W) {
    int t = blockIdx.x * 256 + threadIdx.x;   // 0..2047
    int l = t & 31, tile = (t >> 5) & 3, wn = (t >> 7) & 1, ks = t >> 8;
    int n = l >> 2;
    int k = 16 * tile + 4 * (n >> 1) + 2 * wn + (n & 1);
    int d0 = ks * 16 + 2 * (l & 3);
    __half h[4];
    h[0] = __float2half_rn(W[k * 128 + d0]);
    h[1] = __float2half_rn(W[k * 128 + d0 + 1]);
    h[2] = __float2half_rn(W[k * 128 + d0 + 8]);
    h[3] = __float2half_rn(W[k * 128 + d0 + 9]);
    *reinterpret_cast<uint2*>(&g_Wt[t * 4]) = *reinterpret_cast<uint2*>(h);
}

// ---------------- tile body, MI = m16-tiles per warp (4 = full 128-tok, 2 = half) ----
template <int MI>
__device__ __forceinline__ void tile_body(
    const float* __restrict__ x1, const float* __restrict__ x2,
    float* __restrict__ out, char* shm, uint32_t smb, size_t mbase)
{
    const int tid = threadIdx.x;
    const int lane = tid & 31;
    const int wid = tid >> 5;
    const int wm = wid & 1;        // M-warp 0..1 (MI*16 rows each)
    const int wn = wid >> 1;       // N-warp 0..1
    const int g4 = lane >> 2;
    const int c4 = lane & 3;

    // ---- stage z,s as fp16 (swizzled 256B rows) ----
    {
        const float4* x1v = reinterpret_cast<const float4*>(x1) + mbase * 32;
        const float4* x2v = reinterpret_cast<const float4*>(x2) + mbase * 32;
        #pragma unroll
        for (int it = 0; it < MI * 4; it++) {
            int idx = it * THREADS + tid;
            int m = idx >> 4, c = idx & 15;
            float4 a0 = x1v[m * 32 + c * 2];
            float4 a1 = x1v[m * 32 + c * 2 + 1];
            float4 b0 = x2v[m * 32 + c * 2];
            float4 b1 = x2v[m * 32 + c * 2 + 1];
            half2 zz[4], ss[4];
            zz[0] = __floats2half2_rn(a0.x - b0.x, a0.y - b0.y);
            zz[1] = __floats2half2_rn(a0.z - b0.z, a0.w - b0.w);
            zz[2] = __floats2half2_rn(a1.x - b1.x, a1.y - b1.y);
            zz[3] = __floats2half2_rn(a1.z - b1.z, a1.w - b1.w);
            ss[0] = __floats2half2_rn(a0.x + b0.x, a0.y + b0.y);
            ss[1] = __floats2half2_rn(a0.z + b0.z, a0.w + b0.w);
            ss[2] = __floats2half2_rn(a1.x + b1.x, a1.y + b1.y);
            ss[3] = __floats2half2_rn(a1.z + b1.z, a1.w + b1.w);
            uint32_t so = (uint32_t)(m * 256 + ((c ^ (m & 7)) << 4));
            *reinterpret_cast<uint4*>(shm + ZSH + so) = *reinterpret_cast<uint4*>(zz);
            *reinterpret_cast<uint4*>(shm + SSH + so) = *reinterpret_cast<uint4*>(ss);
        }
    }
    __syncthreads();

    // ---- per-lane A ldmatrix row bases ----
    const int xr = lane & 7;
    uint32_t rowA[MI];
    #pragma unroll
    for (int mi = 0; mi < MI; mi++)
        rowA[mi] = (uint32_t)((wm * (MI * 16) + mi * 16 + ((lane >> 3) & 1) * 8 + xr) * 256);
    const int krelA = lane >> 4;

    const uint4* bv = reinterpret_cast<const uint4*>(g_B);
    const uint2* wv = reinterpret_cast<const uint2*>(g_Wt);

    // ---- Phase L: lin = z @ W^T ----
    {
        float lw[MI][4][4] = {};
        #pragma unroll
        for (int ks = 0; ks < 8; ks++) {
            uint32_t offA = (uint32_t)(((2 * ks + krelA) ^ xr) << 4);
            uint32_t az[MI][4];
            #pragma unroll
            for (int mi = 0; mi < MI; mi++)
                LDSM_X4(az[mi][0], az[mi][1], az[mi][2], az[mi][3],
                        smb + ZSH + rowA[mi] + offA);
            #pragma unroll
            for (int t = 0; t < 4; t++) {
                uint2 w = wv[((ks * 2 + wn) * 4 + t) * 32 + lane];
                uint32_t bw[2] = {w.x, w.y};
                #pragma unroll
                for (int mi = 0; mi < MI; mi++)
                    mma_f16(lw[mi][t], az[mi], bw);
            }
        }
        #pragma unroll
        for (int mi = 0; mi < MI; mi++) {
            size_t m0 = mbase + wm * (MI * 16) + mi * 16 + g4;
            #pragma unroll
            for (int t = 0; t < 4; t++) {
                int k0 = 16 * t + 4 * c4 + 2 * wn;
                *reinterpret_cast<float2*>(&out[m0 * KTOT + k0]) =
                    make_float2(lw[mi][t][0], lw[mi][t][1]);
                *reinterpret_cast<float2*>(&out[(m0 + 8) * KTOT + k0]) =
                    make_float2(lw[mi][t][2], lw[mi][t][3]);
            }
        }
    }

    // ---- main loop: B prefetched one k-step ahead (branchless via pad group) ----
    uint4 v[4];
    #pragma unroll
    for (int j = 0; j < 4; j++) v[j] = bv[(wn * 4 + j) * 32 + lane];

    for (int g = 0; g < NGRP; g++) {
        // hoisted lin prefetch: L2 hit hides under this group's MMA chain
        const int kA = g * 4 + 2 * wn;
        const bool writer = (c4 == (g & 3));
        float2 l0[MI], l1[MI];
        if (writer) {
            #pragma unroll
            for (int mi = 0; mi < MI; mi++) {
                size_t m0 = mbase + wm * (MI * 16) + mi * 16 + g4;
                l0[mi] = *reinterpret_cast<const float2*>(&out[m0 * KTOT + kA]);
                l1[mi] = *reinterpret_cast<const float2*>(&out[(m0 + 8) * KTOT + kA]);
            }
        }

        float zp[MI][4][4] = {};
        float sq[MI][4][4] = {};

        #pragma unroll
        for (int ks = 0; ks < 8; ks++) {
            // branchless prefetch of next k-step's B (pad group absorbs overrun)
            uint4 vn[4];
            const int bbn = ((g * 8 + ks + 1) * 2 + wn) * 4;
            #pragma unroll
            for (int j = 0; j < 4; j++) vn[j] = bv[(bbn + j) * 32 + lane];

            uint32_t offA = (uint32_t)(((2 * ks + krelA) ^ xr) << 4);
            uint32_t az[MI][4], as_[MI][4];
            #pragma unroll
            for (int mi = 0; mi < MI; mi++) {
                LDSM_X4(az[mi][0], az[mi][1], az[mi][2], az[mi][3],
                        smb + ZSH + rowA[mi] + offA);
                LDSM_X4(as_[mi][0], as_[mi][1], as_[mi][2], as_[mi][3],
                        smb + SSH + rowA[mi] + offA);
            }
            #pragma unroll
            for (int j = 0; j < 4; j++) {
                uint32_t bp[2] = {v[j].x, v[j].y};
                uint32_t bq[2] = {v[j].z, v[j].w};
                #pragma unroll
                for (int mi = 0; mi < MI; mi++) {
                    mma_f16(zp[mi][j], az[mi], bp);
                    mma_f16(sq[mi][j], as_[mi], bq);
                }
            }
            #pragma unroll
            for (int j = 0; j < 4; j++) v[j] = vn[j];
        }

        // ---- epilogue: reduce r, add prefetched lin, store ----
        #pragma unroll
        for (int mi = 0; mi < MI; mi++) {
            float pa0 = zp[mi][0][0]*sq[mi][0][0] + zp[mi][0][1]*sq[mi][0][1]
                      + zp[mi][1][0]*sq[mi][1][0] + zp[mi][1][1]*sq[mi][1][1];
            float pa1 = zp[mi][0][2]*sq[mi][0][2] + zp[mi][0][3]*sq[mi][0][3]
                      + zp[mi][1][2]*sq[mi][1][2] + zp[mi][1][3]*sq[mi][1][3];
            float pb0 = zp[mi][2][0]*sq[mi][2][0] + zp[mi][2][1]*sq[mi][2][1]
                      + zp[mi][3][0]*sq[mi][3][0] + zp[mi][3][1]*sq[mi][3][1];
            float pb1 = zp[mi][2][2]*sq[mi][2][2] + zp[mi][2][3]*sq[mi][2][3]
                      + zp[mi][3][2]*sq[mi][3][2] + zp[mi][3][3]*sq[mi][3][3];
            pa0 += __shfl_xor_sync(~0u, pa0, 1); pa0 += __shfl_xor_sync(~0u, pa0, 2);
            pa1 += __shfl_xor_sync(~0u, pa1, 1); pa1 += __shfl_xor_sync(~0u, pa1, 2);
            pb0 += __shfl_xor_sync(~0u, pb0, 1); pb0 += __shfl_xor_sync(~0u, pb0, 2);
            pb1 += __shfl_xor_sync(~0u, pb1, 1); pb1 += __shfl_xor_sync(~0u, pb1, 2);
            if (writer) {
                size_t m0 = mbase + wm * (MI * 16) + mi * 16 + g4;
                *reinterpret_cast<float2*>(&out[m0 * KTOT + kA]) =
                    make_float2(l0[mi].x + pa0, l0[mi].y + pb0);
                *reinterpret_cast<float2*>(&out[(m0 + 8) * KTOT + kA]) =
                    make_float2(l1[mi].x + pa1, l1[mi].y + pb1);
            }
        }
    }
}

// ---------------- main kernel ----------------
__global__ __launch_bounds__(THREADS, 2)
void antisym_h(const float* __restrict__ x1, const float* __restrict__ x2,
               float* __restrict__ out, int fullCTAs)
{
    extern __shared__ char shm[];
    const uint32_t smb = smem_u32(shm);
    const int bid = blockIdx.x;

    if (bid < fullCTAs) {
        tile_body<4>(x1, x2, out, shm, smb, (size_t)bid * 128);
    } else {
        tile_body<2>(x1, x2, out, shm, smb,
                     (size_t)fullCTAs * 128 + (size_t)(bid - fullCTAs) * 64);
    }
}

extern "C" void kernel_launch(void* const* d_in, const int* in_sizes, int n_in,
                              void* d_out, int out_size)
{
    const float* x1 = (const float*)d_in[0];
    const float* x2 = (const float*)d_in[1];
    const float* W  = (const float*)d_in[2];
    const float* P  = (const float*)d_in[3];
    const float* Q  = (const float*)d_in[4];
    float* out = (float*)d_out;

    pack_b<<<128, 256>>>(P, Q);
    pad_b<<<8, 256>>>();
    pack_w<<<8, 256>>>(W);

    const int tokens = in_sizes[0] / D128;        // 131072
    const int tiles128 = tokens / 128;            // 1024
    const int CONC = 296;                         // 148 SMs x occ 2
    int full = (tiles128 / CONC) * CONC;          // 888
    if (full == 0) full = tiles128;
    const int smallCTAs = (tokens - full * 128) / 64;   // 272
    const int grid = full + smallCTAs;            // 1160

    cudaFuncSetAttribute(antisym_h,
                         cudaFuncAttributeMaxDynamicSharedMemorySize, SMEM_BYTES);
    antisym_h<<<grid, THREADS, SMEM_BYTES>>>(x1, x2, out, full);
}

// round 14
// speedup vs baseline: 1.1069x; 1.0073x over previous
#include <cuda_runtime.h>
#include <cuda_fp16.h>
#include <cstdint>

// AntisymmetricLayer via fp16 mma.sync.m16n8k16 (fp32 accum).
//   z = x1-x2, s = x1+x2 (fp16)
//   Phase L: lin = z @ W^T -> SMEM (each lane keeps exactly its own epilogue values)
//   Main: per 4-k group, zP = z @ P^T, sQ = s @ Q^T; epilogue: out = lin(LDS) + sum_r zP*sQ
// r14 = r9 (195us) + lin parked in smem (kills the exposed L2 RMW read; epilogue is a
// pure store; no registers live across the group loop) + branchless pad B prefetch.
// MTILE=128, 4 warps 2Mx2N, warp tile 64x32, occ 2; B fragment-packed from L2;
// no staging, no main-loop barriers; mixed grid 888 full + 272 half tiles.

#define D128 128
#define KTOT 64
#define NGRP 16
#define THREADS 128

#define ZSH 0
#define SSH 32768
#define LIN 65536
#define SMEM_BYTES 98304   // 96KB -> still 2 CTAs/SM (192KB <= 228KB)

// fragment-packed B (+1 zero pad group for branchless prefetch):
// [g][ks][wn][j] blocks of 512B (32 lanes x 16B = P.b0,b1,Q.b0,b1)
__device__ __align__(16) __half g_B[(16 + 1) * 8 * 2 * 4 * 256];
// fragment-packed W: [ks][wn][t] blocks of 256B (32 lanes x 8B)
__device__ __align__(16) __half g_Wt[8 * 2 * 4 * 128];

__device__ __forceinline__ uint32_t smem_u32(const void* p) {
    uint32_t a;
    asm("{ .reg .u64 t; cvta.to.shared.u64 t, %1; cvt.u32.u64 %0, t; }" : "=r"(a) : "l"(p));
    return a;
}

#define LDSM_X4(r0, r1, r2, r3, a) \
    asm volatile("ldmatrix.sync.aligned.m8n8.x4.shared.b16 {%0,%1,%2,%3}, [%4];" \
        : "=r"(r0), "=r"(r1), "=r"(r2), "=r"(r3) : "r"(a))

__device__ __forceinline__ void mma_f16(float* d, const uint32_t* a, const uint32_t* b) {
    asm volatile("mma.sync.aligned.m16n8k16.row.col.f32.f16.f16.f32 "
                 "{%0,%1,%2,%3}, {%4,%5,%6,%7}, {%8,%9}, {%0,%1,%2,%3};"
                 : "+f"(d[0]), "+f"(d[1]), "+f"(d[2]), "+f"(d[3])
                 : "r"(a[0]), "r"(a[1]), "r"(a[2]), "r"(a[3]),
                   "r"(b[0]), "r"(b[1]));
}

// ---- pack P,Q into fragment order ----
__global__ void pack_b(const float* __restrict__ P, const float* __restrict__ Q) {
    int t = blockIdx.x * 256 + threadIdx.x;   // 0..32767
    int l = t & 31, j = (t >> 5) & 3, wn = (t >> 7) & 1, ks = (t >> 8) & 7, g = t >> 11;
    int c = wn * 32 + j * 8 + (l >> 2);
    int k = g * 4 + (c >> 4), r = c & 15;
    int d0 = ks * 16 + 2 * (l & 3);
    __half h[8];
    h[0] = __float2half_rn(P[(k * 128 + d0) * 16 + r]);
    h[1] = __float2half_rn(P[(k * 128 + d0 + 1) * 16 + r]);
    h[2] = __float2half_rn(P[(k * 128 + d0 + 8) * 16 + r]);
    h[3] = __float2half_rn(P[(k * 128 + d0 + 9) * 16 + r]);
    h[4] = __float2half_rn(Q[(k * 128 + d0) * 16 + r]);
    h[5] = __float2half_rn(Q[(k * 128 + d0 + 1) * 16 + r]);
    h[6] = __float2half_rn(Q[(k * 128 + d0 + 8) * 16 + r]);
    h[7] = __float2half_rn(Q[(k * 128 + d0 + 9) * 16 + r]);
    *reinterpret_cast<uint4*>(&g_B[t * 8]) = *reinterpret_cast<uint4*>(h);
}

// ---- zero the pad group ----
__global__ void pad_b() {
    int t = blockIdx.x * 256 + threadIdx.x;   // 0..2047
    *reinterpret_cast<uint4*>(&g_B[(16 * 8 * 2 * 4 * 256) + t * 8]) =
        make_uint4(0u, 0u, 0u, 0u);
}

// ---- pack W ----
__global__ void pack_w(const float* __restrict__ W) {
    int t = blockIdx.x * 256 + threadIdx.x;   // 0..2047
    int l = t & 31, tile = (t >> 5) & 3, wn = (t >> 7) & 1, ks = t >> 8;
    int n = l >> 2;
    int k = 16 * tile + 4 * (n >> 1) + 2 * wn + (n & 1);
    int d0 = ks * 16 + 2 * (l & 3);
    __half h[4];
    h[0] = __float2half_rn(W[k * 128 + d0]);
    h[1] = __float2half_rn(W[k * 128 + d0 + 1]);
    h[2] = __float2half_rn(W[k * 128 + d0 + 8]);
    h[3] = __float2half_rn(W[k * 128 + d0 + 9]);
    *reinterpret_cast<uint2*>(&g_Wt[t * 4]) = *reinterpret_cast<uint2*>(h);
}

// ---------------- tile body, MI = m16-tiles per warp (4 = full 128-tok, 2 = half) ----
template <int MI>
__device__ __forceinline__ void tile_body(
    const float* __restrict__ x1, const float* __restrict__ x2,
    float* __restrict__ out, char* shm, uint32_t smb, size_t mbase)
{
    const int tid = threadIdx.x;
    const int lane = tid & 31;
    const int wid = tid >> 5;
    const int wm = wid & 1;        // M-warp 0..1 (MI*16 rows each)
    const int wn = wid >> 1;       // N-warp 0..1
    const int g4 = lane >> 2;
    const int c4 = lane & 3;

    // ---- stage z,s as fp16 (swizzled 256B rows) ----
    {
        const float4* x1v = reinterpret_cast<const float4*>(x1) + mbase * 32;
        const float4* x2v = reinterpret_cast<const float4*>(x2) + mbase * 32;
        #pragma unroll
        for (int it = 0; it < MI * 4; it++) {
            int idx = it * THREADS + tid;
            int m = idx >> 4, c = idx & 15;
            float4 a0 = x1v[m * 32 + c * 2];
            float4 a1 = x1v[m * 32 + c * 2 + 1];
            float4 b0 = x2v[m * 32 + c * 2];
            float4 b1 = x2v[m * 32 + c * 2 + 1];
            half2 zz[4], ss[4];
            zz[0] = __floats2half2_rn(a0.x - b0.x, a0.y - b0.y);
            zz[1] = __floats2half2_rn(a0.z - b0.z, a0.w - b0.w);
            zz[2] = __floats2half2_rn(a1.x - b1.x, a1.y - b1.y);
            zz[3] = __floats2half2_rn(a1.z - b1.z, a1.w - b1.w);
            ss[0] = __floats2half2_rn(a0.x + b0.x, a0.y + b0.y);
            ss[1] = __floats2half2_rn(a0.z + b0.z, a0.w + b0.w);
            ss[2] = __floats2half2_rn(a1.x + b1.x, a1.y + b1.y);
            ss[3] = __floats2half2_rn(a1.z + b1.z, a1.w + b1.w);
            uint32_t so = (uint32_t)(m * 256 + ((c ^ (m & 7)) << 4));
            *reinterpret_cast<uint4*>(shm + ZSH + so) = *reinterpret_cast<uint4*>(zz);
            *reinterpret_cast<uint4*>(shm + SSH + so) = *reinterpret_cast<uint4*>(ss);
        }
    }
    __syncthreads();

    // ---- per-lane A ldmatrix row bases ----
    const int xr = lane & 7;
    uint32_t rowA[MI];
    #pragma unroll
    for (int mi = 0; mi < MI; mi++)
        rowA[mi] = (uint32_t)((wm * (MI * 16) + mi * 16 + ((lane >> 3) & 1) * 8 + xr) * 256);
    const int krelA = lane >> 4;

    const uint4* bv = reinterpret_cast<const uint4*>(g_B);
    const uint2* wv = reinterpret_cast<const uint2*>(g_Wt);
    float* linsh = reinterpret_cast<float*>(shm + LIN);

    // ---- Phase L: lin = z @ W^T -> smem (same-lane write/read, no barrier needed) ----
    {
        float lw[MI][4][4] = {};
        #pragma unroll
        for (int ks = 0; ks < 8; ks++) {
            uint32_t offA = (uint32_t)(((2 * ks + krelA) ^ xr) << 4);
            uint32_t az[MI][4];
            #pragma unroll
            for (int mi = 0; mi < MI; mi++)
                LDSM_X4(az[mi][0], az[mi][1], az[mi][2], az[mi][3],
                        smb + ZSH + rowA[mi] + offA);
            #pragma unroll
            for (int t = 0; t < 4; t++) {
                uint2 w = wv[((ks * 2 + wn) * 4 + t) * 32 + lane];
                uint32_t bw[2] = {w.x, w.y};
                #pragma unroll
                for (int mi = 0; mi < MI; mi++)
                    mma_f16(lw[mi][t], az[mi], bw);
            }
        }
        #pragma unroll
        for (int mi = 0; mi < MI; mi++) {
            int mloc = wm * (MI * 16) + mi * 16 + g4;
            #pragma unroll
            for (int t = 0; t < 4; t++) {
                int k0 = 16 * t + 4 * c4 + 2 * wn;
                *reinterpret_cast<float2*>(&linsh[mloc * KTOT + k0]) =
                    make_float2(lw[mi][t][0], lw[mi][t][1]);
                *reinterpret_cast<float2*>(&linsh[(mloc + 8) * KTOT + k0]) =
                    make_float2(lw[mi][t][2], lw[mi][t][3]);
            }
        }
    }

    // ---- main loop: B prefetched one k-step ahead (branchless via pad group) ----
    uint4 v[4];
    #pragma unroll
    for (int j = 0; j < 4; j++) v[j] = bv[(wn * 4 + j) * 32 + lane];

    for (int g = 0; g < NGRP; g++) {
        float zp[MI][4][4] = {};
        float sq[MI][4][4] = {};

        #pragma unroll
        for (int ks = 0; ks < 8; ks++) {
            // branchless prefetch of next k-step's B (pad group absorbs overrun)
            uint4 vn[4];
            const int bbn = ((g * 8 + ks + 1) * 2 + wn) * 4;
            #pragma unroll
            for (int j = 0; j < 4; j++) vn[j] = bv[(bbn + j) * 32 + lane];

            uint32_t offA = (uint32_t)(((2 * ks + krelA) ^ xr) << 4);
            uint32_t az[MI][4], as_[MI][4];
            #pragma unroll
            for (int mi = 0; mi < MI; mi++) {
                LDSM_X4(az[mi][0], az[mi][1], az[mi][2], az[mi][3],
                        smb + ZSH + rowA[mi] + offA);
                LDSM_X4(as_[mi][0], as_[mi][1], as_[mi][2], as_[mi][3],
                        smb + SSH + rowA[mi] + offA);
            }
            #pragma unroll
            for (int j = 0; j < 4; j++) {
                uint32_t bp[2] = {v[j].x, v[j].y};
                uint32_t bq[2] = {v[j].z, v[j].w};
                #pragma unroll
                for (int mi = 0; mi < MI; mi++) {
                    mma_f16(zp[mi][j], az[mi], bp);
                    mma_f16(sq[mi][j], as_[mi], bq);
                }
            }
            #pragma unroll
            for (int j = 0; j < 4; j++) v[j] = vn[j];
        }

        // ---- epilogue: reduce r, add lin from smem (LDS hit), pure store ----
        const int kA = g * 4 + 2 * wn;
        const bool writer = (c4 == (g & 3));
        #pragma unroll
        for (int mi = 0; mi < MI; mi++) {
            float pa0 = zp[mi][0][0]*sq[mi][0][0] + zp[mi][0][1]*sq[mi][0][1]
                      + zp[mi][1][0]*sq[mi][1][0] + zp[mi][1][1]*sq[mi][1][1];
            float pa1 = zp[mi][0][2]*sq[mi][0][2] + zp[mi][0][3]*sq[mi][0][3]
                      + zp[mi][1][2]*sq[mi][1][2] + zp[mi][1][3]*sq[mi][1][3];
            float pb0 = zp[mi][2][0]*sq[mi][2][0] + zp[mi][2][1]*sq[mi][2][1]
                      + zp[mi][3][0]*sq[mi][3][0] + zp[mi][3][1]*sq[mi][3][1];
            float pb1 = zp[mi][2][2]*sq[mi][2][2] + zp[mi][2][3]*sq[mi][2][3]
                      + zp[mi][3][2]*sq[mi][3][2] + zp[mi][3][3]*sq[mi][3][3];
            pa0 += __shfl_xor_sync(~0u, pa0, 1); pa0 += __shfl_xor_sync(~0u, pa0, 2);
            pa1 += __shfl_xor_sync(~0u, pa1, 1); pa1 += __shfl_xor_sync(~0u, pa1, 2);
            pb0 += __shfl_xor_sync(~0u, pb0, 1); pb0 += __shfl_xor_sync(~0u, pb0, 2);
            pb1 += __shfl_xor_sync(~0u, pb1, 1); pb1 += __shfl_xor_sync(~0u, pb1, 2);
            if (writer) {
                int mloc = wm * (MI * 16) + mi * 16 + g4;
                size_t m0 = mbase + mloc;
                float2 l0 = *reinterpret_cast<const float2*>(&linsh[mloc * KTOT + kA]);
                float2 l1 = *reinterpret_cast<const float2*>(&linsh[(mloc + 8) * KTOT + kA]);
                *reinterpret_cast<float2*>(&out[m0 * KTOT + kA]) =
                    make_float2(l0.x + pa0, l0.y + pb0);
                *reinterpret_cast<float2*>(&out[(m0 + 8) * KTOT + kA]) =
                    make_float2(l1.x + pa1, l1.y + pb1);
            }
        }
    }
}

// ---------------- main kernel ----------------
__global__ __launch_bounds__(THREADS, 2)
void antisym_h(const float* __restrict__ x1, const float* __restrict__ x2,
               float* __restrict__ out, int fullCTAs)
{
    extern __shared__ char shm[];
    const uint32_t smb = smem_u32(shm);
    const int bid = blockIdx.x;

    if (bid < fullCTAs) {
        tile_body<4>(x1, x2, out, shm, smb, (size_t)bid * 128);
    } else {
        tile_body<2>(x1, x2, out, shm, smb,
                     (size_t)fullCTAs * 128 + (size_t)(bid - fullCTAs) * 64);
    }
}

extern "C" void kernel_launch(void* const* d_in, const int* in_sizes, int n_in,
                              void* d_out, int out_size)
{
    const float* x1 = (const float*)d_in[0];
    const float* x2 = (const float*)d_in[1];
    const float* W  = (const float*)d_in[2];
    const float* P  = (const float*)d_in[3];
    const float* Q  = (const float*)d_in[4];
    float* out = (float*)d_out;

    pack_b<<<128, 256>>>(P, Q);
    pad_b<<<8, 256>>>();
    pack_w<<<8, 256>>>(W);

    const int tokens = in_sizes[0] / D128;        // 131072
    const int tiles128 = tokens / 128;            // 1024
    const int CONC = 296;                         // 148 SMs x occ 2
    int full = (tiles128 / CONC) * CONC;          // 888
    if (full == 0) full = tiles128;
    const int smallCTAs = (tokens - full * 128) / 64;   // 272
    const int grid = full + smallCTAs;            // 1160

    cudaFuncSetAttribute(antisym_h,
                         cudaFuncAttributeMaxDynamicSharedMemorySize, SMEM_BYTES);
    antisym_h<<<grid, THREADS, SMEM_BYTES>>>(x1, x2, out, full);
}

// round 15
// speedup vs baseline: 1.1435x; 1.0331x over previous
#include <cuda_runtime.h>
#include <cuda_fp16.h>
#include <cstdint>

// AntisymmetricLayer via fp16 mma.sync.m16n8k16 (fp32 accum).
//   z = x1-x2, s = x1+x2 (fp16)
//   Phase L: lin = z @ W^T -> SMEM (same-lane write/read)
//   Main: per 4-k group, zP = z @ P^T, sQ = s @ Q^T; epilogue: out = lin(LDS) + sum_r zP*sQ
// r15 = r14 minus the B-prefetch register chain (-16 regs, aiming under the spill
// threshold; B is L1-hot and loaded at k-step top), plus a single merged pack kernel.
// MTILE=128, 4 warps 2Mx2N, warp tile 64x32, occ 2; B fragment-packed from L1/L2;
// no staging, no main-loop barriers; mixed grid 888 full + 272 half tiles.

#define D128 128
#define KTOT 64
#define NGRP 16
#define THREADS 128

#define ZSH 0
#define SSH 32768
#define LIN 65536
#define SMEM_BYTES 98304   // 96KB -> 2 CTAs/SM

// fragment-packed B: [g][ks][wn][j] blocks of 512B (32 lanes x 16B = P.b0,b1,Q.b0,b1)
__device__ __align__(16) __half g_B[16 * 8 * 2 * 4 * 256];
// fragment-packed W: [ks][wn][t] blocks of 256B (32 lanes x 8B)
__device__ __align__(16) __half g_Wt[8 * 2 * 4 * 128];

__device__ __forceinline__ uint32_t smem_u32(const void* p) {
    uint32_t a;
    asm("{ .reg .u64 t; cvta.to.shared.u64 t, %1; cvt.u32.u64 %0, t; }" : "=r"(a) : "l"(p));
    return a;
}

#define LDSM_X4(r0, r1, r2, r3, a) \
    asm volatile("ldmatrix.sync.aligned.m8n8.x4.shared.b16 {%0,%1,%2,%3}, [%4];" \
        : "=r"(r0), "=r"(r1), "=r"(r2), "=r"(r3) : "r"(a))

__device__ __forceinline__ void mma_f16(float* d, const uint32_t* a, const uint32_t* b) {
    asm volatile("mma.sync.aligned.m16n8k16.row.col.f32.f16.f16.f32 "
                 "{%0,%1,%2,%3}, {%4,%5,%6,%7}, {%8,%9}, {%0,%1,%2,%3};"
                 : "+f"(d[0]), "+f"(d[1]), "+f"(d[2]), "+f"(d[3])
                 : "r"(a[0]), "r"(a[1]), "r"(a[2]), "r"(a[3]),
                   "r"(b[0]), "r"(b[1]));
}

// ---- ONE pack kernel: t<32768 -> B; t<34816 -> W; (grid covers 36864 threads) ----
__global__ void pack_all(const float* __restrict__ P, const float* __restrict__ Q,
                         const float* __restrict__ W) {
    int t = blockIdx.x * 256 + threadIdx.x;
    if (t < 32768) {
        int l = t & 31, j = (t >> 5) & 3, wn = (t >> 7) & 1, ks = (t >> 8) & 7, g = t >> 11;
        int c = wn * 32 + j * 8 + (l >> 2);
        int k = g * 4 + (c >> 4), r = c & 15;
        int d0 = ks * 16 + 2 * (l & 3);
        __half h[8];
        h[0] = __float2half_rn(P[(k * 128 + d0) * 16 + r]);
        h[1] = __float2half_rn(P[(k * 128 + d0 + 1) * 16 + r]);
        h[2] = __float2half_rn(P[(k * 128 + d0 + 8) * 16 + r]);
        h[3] = __float2half_rn(P[(k * 128 + d0 + 9) * 16 + r]);
        h[4] = __float2half_rn(Q[(k * 128 + d0) * 16 + r]);
        h[5] = __float2half_rn(Q[(k * 128 + d0 + 1) * 16 + r]);
        h[6] = __float2half_rn(Q[(k * 128 + d0 + 8) * 16 + r]);
        h[7] = __float2half_rn(Q[(k * 128 + d0 + 9) * 16 + r]);
        *reinterpret_cast<uint4*>(&g_B[t * 8]) = *reinterpret_cast<uint4*>(h);
    } else if (t < 34816) {
        int u = t - 32768;   // 0..2047 -> W
        int l = u & 31, tile = (u >> 5) & 3, wn = (u >> 7) & 1, ks = u >> 8;
        int n = l >> 2;
        int k = 16 * tile + 4 * (n >> 1) + 2 * wn + (n & 1);
        int d0 = ks * 16 + 2 * (l & 3);
        __half h[4];
        h[0] = __float2half_rn(W[k * 128 + d0]);
        h[1] = __float2half_rn(W[k * 128 + d0 + 1]);
        h[2] = __float2half_rn(W[k * 128 + d0 + 8]);
        h[3] = __float2half_rn(W[k * 128 + d0 + 9]);
        *reinterpret_cast<uint2*>(&g_Wt[u * 4]) = *reinterpret_cast<uint2*>(h);
    }
}

// ---------------- tile body, MI = m16-tiles per warp (4 = full 128-tok, 2 = half) ----
template <int MI>
__device__ __forceinline__ void tile_body(
    const float* __restrict__ x1, const float* __restrict__ x2,
    float* __restrict__ out, char* shm, uint32_t smb, size_t mbase)
{
    const int tid = threadIdx.x;
    const int lane = tid & 31;
    const int wid = tid >> 5;
    const int wm = wid & 1;        // M-warp 0..1 (MI*16 rows each)
    const int wn = wid >> 1;       // N-warp 0..1
    const int g4 = lane >> 2;
    const int c4 = lane & 3;

    // ---- stage z,s as fp16 (swizzled 256B rows) ----
    {
        const float4* x1v = reinterpret_cast<const float4*>(x1) + mbase * 32;
        const float4* x2v = reinterpret_cast<const float4*>(x2) + mbase * 32;
        #pragma unroll
        for (int it = 0; it < MI * 4; it++) {
            int idx = it * THREADS + tid;
            int m = idx >> 4, c = idx & 15;
            float4 a0 = x1v[m * 32 + c * 2];
            float4 a1 = x1v[m * 32 + c * 2 + 1];
            float4 b0 = x2v[m * 32 + c * 2];
            float4 b1 = x2v[m * 32 + c * 2 + 1];
            half2 zz[4], ss[4];
            zz[0] = __floats2half2_rn(a0.x - b0.x, a0.y - b0.y);
            zz[1] = __floats2half2_rn(a0.z - b0.z, a0.w - b0.w);
            zz[2] = __floats2half2_rn(a1.x - b1.x, a1.y - b1.y);
            zz[3] = __floats2half2_rn(a1.z - b1.z, a1.w - b1.w);
            ss[0] = __floats2half2_rn(a0.x + b0.x, a0.y + b0.y);
            ss[1] = __floats2half2_rn(a0.z + b0.z, a0.w + b0.w);
            ss[2] = __floats2half2_rn(a1.x + b1.x, a1.y + b1.y);
            ss[3] = __floats2half2_rn(a1.z + b1.z, a1.w + b1.w);
            uint32_t so = (uint32_t)(m * 256 + ((c ^ (m & 7)) << 4));
            *reinterpret_cast<uint4*>(shm + ZSH + so) = *reinterpret_cast<uint4*>(zz);
            *reinterpret_cast<uint4*>(shm + SSH + so) = *reinterpret_cast<uint4*>(ss);
        }
    }
    __syncthreads();

    // ---- per-lane A ldmatrix row bases ----
    const int xr = lane & 7;
    uint32_t rowA[MI];
    #pragma unroll
    for (int mi = 0; mi < MI; mi++)
        rowA[mi] = (uint32_t)((wm * (MI * 16) + mi * 16 + ((lane >> 3) & 1) * 8 + xr) * 256);
    const int krelA = lane >> 4;

    const uint4* bv = reinterpret_cast<const uint4*>(g_B);
    const uint2* wv = reinterpret_cast<const uint2*>(g_Wt);
    float* linsh = reinterpret_cast<float*>(shm + LIN);

    // ---- Phase L: lin = z @ W^T -> smem ----
    {
        float lw[MI][4][4] = {};
        #pragma unroll
        for (int ks = 0; ks < 8; ks++) {
            uint32_t offA = (uint32_t)(((2 * ks + krelA) ^ xr) << 4);
            uint32_t az[MI][4];
            #pragma unroll
            for (int mi = 0; mi < MI; mi++)
                LDSM_X4(az[mi][0], az[mi][1], az[mi][2], az[mi][3],
                        smb + ZSH + rowA[mi] + offA);
            #pragma unroll
            for (int t = 0; t < 4; t++) {
                uint2 w = wv[((ks * 2 + wn) * 4 + t) * 32 + lane];
                uint32_t bw[2] = {w.x, w.y};
                #pragma unroll
                for (int mi = 0; mi < MI; mi++)
                    mma_f16(lw[mi][t], az[mi], bw);
            }
        }
        #pragma unroll
        for (int mi = 0; mi < MI; mi++) {
            int mloc = wm * (MI * 16) + mi * 16 + g4;
            #pragma unroll
            for (int t = 0; t < 4; t++) {
                int k0 = 16 * t + 4 * c4 + 2 * wn;
                *reinterpret_cast<float2*>(&linsh[mloc * KTOT + k0]) =
                    make_float2(lw[mi][t][0], lw[mi][t][1]);
                *reinterpret_cast<float2*>(&linsh[(mloc + 8) * KTOT + k0]) =
                    make_float2(lw[mi][t][2], lw[mi][t][3]);
            }
        }
    }

    // ---- main loop: B loaded at k-step top (L1-hot), no prefetch registers ----
    for (int g = 0; g < NGRP; g++) {
        float zp[MI][4][4] = {};
        float sq[MI][4][4] = {};

        #pragma unroll
        for (int ks = 0; ks < 8; ks++) {
            uint4 v[4];
            const int bb = ((g * 8 + ks) * 2 + wn) * 4;
            #pragma unroll
            for (int j = 0; j < 4; j++) v[j] = bv[(bb + j) * 32 + lane];

            uint32_t offA = (uint32_t)(((2 * ks + krelA) ^ xr) << 4);
            uint32_t az[MI][4], as_[MI][4];
            #pragma unroll
            for (int mi = 0; mi < MI; mi++) {
                LDSM_X4(az[mi][0], az[mi][1], az[mi][2], az[mi][3],
                        smb + ZSH + rowA[mi] + offA);
                LDSM_X4(as_[mi][0], as_[mi][1], as_[mi][2], as_[mi][3],
                        smb + SSH + rowA[mi] + offA);
            }
            #pragma unroll
            for (int j = 0; j < 4; j++) {
                uint32_t bp[2] = {v[j].x, v[j].y};
                uint32_t bq[2] = {v[j].z, v[j].w};
                #pragma unroll
                for (int mi = 0; mi < MI; mi++) {
                    mma_f16(zp[mi][j], az[mi], bp);
                    mma_f16(sq[mi][j], as_[mi], bq);
                }
            }
        }

        // ---- epilogue: reduce r, add lin from smem, pure store ----
        const int kA = g * 4 + 2 * wn;
        const bool writer = (c4 == (g & 3));
        #pragma unroll
        for (int mi = 0; mi < MI; mi++) {
            float pa0 = zp[mi][0][0]*sq[mi][0][0] + zp[mi][0][1]*sq[mi][0][1]
                      + zp[mi][1][0]*sq[mi][1][0] + zp[mi][1][1]*sq[mi][1][1];
            float pa1 = zp[mi][0][2]*sq[mi][0][2] + zp[mi][0][3]*sq[mi][0][3]
                      + zp[mi][1][2]*sq[mi][1][2] + zp[mi][1][3]*sq[mi][1][3];
            float pb0 = zp[mi][2][0]*sq[mi][2][0] + zp[mi][2][1]*sq[mi][2][1]
                      + zp[mi][3][0]*sq[mi][3][0] + zp[mi][3][1]*sq[mi][3][1];
            float pb1 = zp[mi][2][2]*sq[mi][2][2] + zp[mi][2][3]*sq[mi][2][3]
                      + zp[mi][3][2]*sq[mi][3][2] + zp[mi][3][3]*sq[mi][3][3];
            pa0 += __shfl_xor_sync(~0u, pa0, 1); pa0 += __shfl_xor_sync(~0u, pa0, 2);
            pa1 += __shfl_xor_sync(~0u, pa1, 1); pa1 += __shfl_xor_sync(~0u, pa1, 2);
            pb0 += __shfl_xor_sync(~0u, pb0, 1); pb0 += __shfl_xor_sync(~0u, pb0, 2);
            pb1 += __shfl_xor_sync(~0u, pb1, 1); pb1 += __shfl_xor_sync(~0u, pb1, 2);
            if (writer) {
                int mloc = wm * (MI * 16) + mi * 16 + g4;
                size_t m0 = mbase + mloc;
                float2 l0 = *reinterpret_cast<const float2*>(&linsh[mloc * KTOT + kA]);
                float2 l1 = *reinterpret_cast<const float2*>(&linsh[(mloc + 8) * KTOT + kA]);
                *reinterpret_cast<float2*>(&out[m0 * KTOT + kA]) =
                    make_float2(l0.x + pa0, l0.y + pb0);
                *reinterpret_cast<float2*>(&out[(m0 + 8) * KTOT + kA]) =
                    make_float2(l1.x + pa1, l1.y + pb1);
            }
        }
    }
}

// ---------------- main kernel ----------------
__global__ __launch_bounds__(THREADS, 2)
void antisym_h(const float* __restrict__ x1, const float* __restrict__ x2,
               float* __restrict__ out, int fullCTAs)
{
    extern __shared__ char shm[];
    const uint32_t smb = smem_u32(shm);
    const int bid = blockIdx.x;

    if (bid < fullCTAs) {
        tile_body<4>(x1, x2, out, shm, smb, (size_t)bid * 128);
    } else {
        tile_body<2>(x1, x2, out, shm, smb,
                     (size_t)fullCTAs * 128 + (size_t)(bid - fullCTAs) * 64);
    }
}

extern "C" void kernel_launch(void* const* d_in, const int* in_sizes, int n_in,
                              void* d_out, int out_size)
{
    const float* x1 = (const float*)d_in[0];
    const float* x2 = (const float*)d_in[1];
    const float* W  = (const float*)d_in[2];
    const float* P  = (const float*)d_in[3];
    const float* Q  = (const float*)d_in[4];
    float* out = (float*)d_out;

    pack_all<<<144, 256>>>(P, Q, W);

    const int tokens = in_sizes[0] / D128;        // 131072
    const int tiles128 = tokens / 128;            // 1024
    const int CONC = 296;                         // 148 SMs x occ 2
    int full = (tiles128 / CONC) * CONC;          // 888
    if (full == 0) full = tiles128;
    const int smallCTAs = (tokens - full * 128) / 64;   // 272
    const int grid = full + smallCTAs;            // 1160

    cudaFuncSetAttribute(antisym_h,
                         cudaFuncAttributeMaxDynamicSharedMemorySize, SMEM_BYTES);
    antisym_h<<<grid, THREADS, SMEM_BYTES>>>(x1, x2, out, full);
}